// round 17
// baseline (speedup 1.0000x reference)
#include <cuda_runtime.h>
#include <cuda_bf16.h>
#include <cuda_fp16.h>
#include <cstdint>

// CondConv2D: B=16, C=64, H=W=256, E=4, 3x3, pad=1.
// Fused persistent kernel, 148 CTAs x 512 threads:
//   Phase 1: pool   Phase 2: routing+mix   Phase 3: conv
// Conv (phase 3): implicit GEMM on mma.sync.m16n8k16.f16 (f32 acc).
//   rt(HMMA) = 8 cyc/SMSP -> tensor floor ~134us; R13 was LDS-crossbar-bound
//   (2 LDS.32/MMA). This version: warp tile 64pix x 32oc (mt=4) -> 1.5 LDS/MMA,
//   TWO output rows (h, h+1) per iteration (16 warps cover 512x64), 2 barriers
//   per 2 rows. A-ring: 4 slots hold rows h-1..h+2; rows h+3/h+4 are staged
//   after sync1/sync2 into the slots proven dead by then:
//     slot (h+3)&3 == (h-1)&3 : read only by kh=0 group (before sync1)
//     slot (h+4)&3 == (h)&3   : read by kh=0(ro1)+kh=1(ro0) groups (before sync2)

#define B_     16
#define CIN    64
#define COUT   64
#define HH     256
#define WW     256
#define HW     (HH * WW)
#define NE     4
#define NCTA   148

#define RA 264                    // A slot row stride (words); 264 % 32 == 8
#define RB 72                     // B row stride (words);      72 % 32 == 8
#define A_SLOTW (16 * RA)         // words per (ih, slot) tile
#define A_RINGW (8 * A_SLOTW)     // 4 slots x 2 ih
#define B_WORDS (288 * RB)        // 6 st x 3 kw x 16 kp rows
#define SMEM_BYTES ((A_RINGW + B_WORDS) * 4)   // 218112 B

#define MIXW (6 * 3 * 16 * COUT)  // 18432 words per batch

__device__ float g_pooled[B_ * CIN];
__device__ __align__(16) uint32_t g_wmix[(size_t)B_ * MIXW];
__device__ unsigned g_bar0, g_bar1;   // monotone barrier tickets

__device__ __forceinline__ void mma_f16(float& d0, float& d1, float& d2, float& d3,
                                        uint32_t a0, uint32_t a1, uint32_t a2, uint32_t a3,
                                        uint32_t b0, uint32_t b1) {
    asm volatile(
        "mma.sync.aligned.m16n8k16.row.col.f32.f16.f16.f32 "
        "{%0,%1,%2,%3}, {%4,%5,%6,%7}, {%8,%9}, {%0,%1,%2,%3};"
        : "+f"(d0), "+f"(d1), "+f"(d2), "+f"(d3)
        : "r"(a0), "r"(a1), "r"(a2), "r"(a3), "r"(b0), "r"(b1));
}

__device__ __forceinline__ uint32_t packh2(float lo, float hi) {
    __half2 h = __floats2half2_rn(lo, hi);
    return *reinterpret_cast<uint32_t*>(&h);
}

__device__ __forceinline__ void grid_barrier(unsigned* bar) {
    __syncthreads();
    if (threadIdx.x == 0) {
        __threadfence();
        unsigned ticket = atomicAdd(bar, 1u);
        unsigned target = (ticket / NCTA + 1u) * NCTA;
        while (*(volatile unsigned*)bar < target) { }
        __threadfence();
    }
    __syncthreads();
}

__global__ __launch_bounds__(512, 1) void fused_kernel(const float* __restrict__ x,
                                                       const float* __restrict__ weight,
                                                       const float* __restrict__ fc_w,
                                                       const float* __restrict__ fc_b,
                                                       float* __restrict__ out) {
    extern __shared__ uint32_t smem[];
    const int tid = threadIdx.x;
    const int wid = tid >> 5;
    const int lid = tid & 31;
    const int cta = blockIdx.x;

    // ================= Phase 1: pool =================
    {
        float* scr = (float*)smem;
        int p0 = (B_ * CIN * cta) / NCTA;
        int p1 = (B_ * CIN * (cta + 1)) / NCTA;
        for (int p = p0; p < p1; p++) {
            const float4* xp = (const float4*)(x + (size_t)p * HW);
            float s = 0.f;
            #pragma unroll 8
            for (int i = tid; i < HW / 4; i += 512) {
                float4 v = __ldg(xp + i);
                s += (v.x + v.y) + (v.z + v.w);
            }
            #pragma unroll
            for (int o = 16; o > 0; o >>= 1) s += __shfl_xor_sync(0xFFFFFFFF, s, o);
            if (lid == 0) scr[wid] = s;
            __syncthreads();
            if (wid == 0) {
                float v = (lid < 16) ? scr[lid] : 0.f;
                #pragma unroll
                for (int o = 8; o > 0; o >>= 1) v += __shfl_xor_sync(0xFFFFFFFF, v, o);
                if (lid == 0) g_pooled[p] = v * (1.f / HW);
            }
            __syncthreads();
        }
    }
    grid_barrier(&g_bar0);

    // ================= Phase 2: routing + mix =================
    {
        float* r_all = (float*)smem;                // [16 b][4 e]
        if (tid < 64) {
            int b = tid >> 2, e = tid & 3;
            float acc = fc_b[e];
            #pragma unroll 8
            for (int c = 0; c < CIN; c++) acc += g_pooled[b * CIN + c] * fc_w[e * CIN + c];
            r_all[tid] = 1.f / (1.f + expf(-acc));
        }
        __syncthreads();

        const size_t estride = (size_t)COUT * CIN * 9;
        const int TOTW = B_ * MIXW;
        int w0 = (int)(((long long)TOTW * cta) / NCTA);
        int w1 = (int)(((long long)TOTW * (cta + 1)) / NCTA);
        for (int gw = w0 + tid; gw < w1; gw += 512) {
            int b    = gw / MIXW;
            int widx = gw - b * MIXW;
            int oc   = widx / 288;
            int rem  = widx - oc * 288;
            int ih   = rem / 144;
            int rem2 = rem - ih * 144;
            int kp   = rem2 / 9;
            int tap  = rem2 - kp * 9;
            int kh = tap / 3, kw = tap - kh * 3;
            int ic = ih * 32 + 2 * kp;
            float r0 = r_all[b * 4 + 0], r1 = r_all[b * 4 + 1];
            float r2 = r_all[b * 4 + 2], r3 = r_all[b * 4 + 3];
            size_t s0 = ((size_t)oc * CIN + ic) * 9 + tap;
            size_t s1 = s0 + 9;
            float v0 = r0 * weight[s0] + r1 * weight[s0 + estride]
                     + r2 * weight[s0 + 2 * estride] + r3 * weight[s0 + 3 * estride];
            float v1 = r0 * weight[s1] + r1 * weight[s1 + estride]
                     + r2 * weight[s1 + 2 * estride] + r3 * weight[s1 + 3 * estride];
            int st = ih * 3 + kh;
            g_wmix[(size_t)b * MIXW + ((st * 3 + kw) * 16 + kp) * 64 + oc] = packh2(v0, v1);
        }
    }
    grid_barrier(&g_bar1);

    // ================= Phase 3: conv =================
    uint32_t* A_ring = smem;                   // [2 ih][4 slot][16 kp][RA]
    uint32_t* B_s    = smem + A_RINGW;         // [288 rows][RB]

    const int g = lid >> 2;
    const int t = lid & 3;
    const int warpN  = wid >> 3;        // 32-oc group (0/1)
    const int rowOff = (wid >> 2) & 1;  // output row h + rowOff
    const int cb     = (wid & 3) * 64;  // 64-pix column base

    uint32_t sbaseB;
    asm("{ .reg .u64 tt; cvta.to.shared.u64 tt, %1; cvt.u32.u64 %0, tt; }"
        : "=r"(sbaseB) : "l"(B_s));

    const int kpA = tid >> 5;           // 0..15
    const int c0A = tid & 31;

    const float* xb = x;
    int b = 0;

    uint32_t au0[8], au1[8];
    auto ldA = [&](int ih, int row, uint32_t* au) {
        bool hv = (unsigned)row < HH;
        int hpc = hv ? row : 0;
        const float2* r0p = (const float2*)(xb + (size_t)(ih * 32 + 2 * kpA) * HW + (size_t)hpc * WW);
        const float2* r1p = r0p + HW / 2;
        #pragma unroll
        for (int i = 0; i < 4; i++) {
            int j = c0A + 32 * i;
            float2 v0 = hv ? __ldg(r0p + j) : make_float2(0.f, 0.f);
            float2 v1 = hv ? __ldg(r1p + j) : make_float2(0.f, 0.f);
            au[2 * i]     = packh2(v0.x, v1.x);
            au[2 * i + 1] = packh2(v0.y, v1.y);
        }
    };
    auto stA = [&](int ih, int slot, const uint32_t* au) {
        uint32_t* Ab = A_ring + (ih * 4 + slot) * A_SLOTW + kpA * RA;
        #pragma unroll
        for (int i = 0; i < 4; i++) {
            int j = c0A + 32 * i;
            Ab[2 * j + 1] = au[2 * i];
            Ab[2 * j + 2] = au[2 * i + 1];
        }
        if (c0A == 0) { Ab[0] = 0u; Ab[257] = 0u; }
    };

    float d[4][4][4];                   // [mt][nt][frag]

    auto computeStage = [&](int ih, int kh, int h) {
        int slot = (h + rowOff - 1 + kh) & 3;
        const uint32_t* Ab = A_ring + (ih * 4 + slot) * A_SLOTW;
        const int st = ih * 3 + kh;
        #pragma unroll
        for (int kw = 0; kw < 3; kw++) {
            const uint32_t* Bb = B_s + (size_t)((st * 3 + kw) * 16) * RB;
            #pragma unroll
            for (int ks = 0; ks < 2; ks++) {
                const int kb = ks * 8;
                uint32_t bf[4][2];
                #pragma unroll
                for (int nt = 0; nt < 4; nt++) {
                    int nb = warpN * 32 + nt * 8 + g;
                    bf[nt][0] = Bb[(kb + t) * RB + nb];
                    bf[nt][1] = Bb[(kb + t + 4) * RB + nb];
                }
                #pragma unroll
                for (int mt = 0; mt < 4; mt++) {
                    int col = cb + mt * 16 + g + kw;
                    uint32_t a0 = Ab[(kb + t) * RA + col];
                    uint32_t a1 = Ab[(kb + t) * RA + col + 8];
                    uint32_t a2 = Ab[(kb + t + 4) * RA + col];
                    uint32_t a3 = Ab[(kb + t + 4) * RA + col + 8];
                    #pragma unroll
                    for (int nt = 0; nt < 4; nt++)
                        mma_f16(d[mt][nt][0], d[mt][nt][1], d[mt][nt][2], d[mt][nt][3],
                                a0, a1, a2, a3, bf[nt][0], bf[nt][1]);
                }
            }
        }
    };

    // ---- globally balanced PAIR slice over (b, h/2) ----
    const int TOTP = B_ * HH / 2;                  // 2048 pairs
    int p0 = (TOTP * cta) / NCTA;
    int p1 = (TOTP * (cta + 1)) / NCTA;
    int p = p0;

    while (p < p1) {
        b = p >> 7;                                // 128 pairs per batch
        int h0 = (p & 127) * 2;
        int segEndP = (p1 < ((b + 1) << 7)) ? p1 : ((b + 1) << 7);
        int h1 = (segEndP - (b << 7)) * 2;
        xb = x + (size_t)b * CIN * HW;
        const uint32_t* wb = g_wmix + (size_t)b * MIXW;

        __syncthreads();   // previous segment finished reading B_s / ring

        // B for this batch (cp.async, once per segment)
        #pragma unroll
        for (int i = 0; i < 9; i++) {
            int idx = tid + 512 * i;
            int row = idx >> 4, q = idx & 15;
            uint32_t dst = sbaseB + (uint32_t)((row * RB + q * 4) * 4);
            asm volatile("cp.async.cg.shared.global [%0], [%1], 16;"
                         :: "r"(dst), "l"(wb + row * 64 + q * 4) : "memory");
        }
        asm volatile("cp.async.commit_group;" ::: "memory");

        // A prologue: rows h0-1 .. h0+2
        #pragma unroll
        for (int rr = 0; rr < 4; rr++) {
            int row = h0 - 1 + rr;
            ldA(0, row, au0); stA(0, row & 3, au0);
            ldA(1, row, au1); stA(1, row & 3, au1);
        }
        asm volatile("cp.async.wait_group 0;" ::: "memory");
        __syncthreads();   // publish prologue ring + B

        for (int h = h0; h < h1; h += 2) {
            #pragma unroll
            for (int mt = 0; mt < 4; mt++)
                #pragma unroll
                for (int nt = 0; nt < 4; nt++)
                    #pragma unroll
                    for (int k = 0; k < 4; k++) d[mt][nt][k] = 0.f;

            // group 1 (kh=0): reads slots (h-1)&3 (ro0), h&3 (ro1)
            ldA(0, h + 3, au0); ldA(1, h + 3, au1);
            computeStage(0, 0, h);
            computeStage(1, 0, h);
            __syncthreads();                     // sync1: slot (h+3)&3==(h-1)&3 now dead
            stA(0, (h + 3) & 3, au0); stA(1, (h + 3) & 3, au1);

            // group 2 (kh=1): reads slots h&3 (ro0), (h+1)&3 (ro1)
            ldA(0, h + 4, au0); ldA(1, h + 4, au1);
            computeStage(0, 1, h);
            computeStage(1, 1, h);
            __syncthreads();                     // sync2: slot (h+4)&3==h&3 now dead
            stA(0, (h + 4) & 3, au0); stA(1, (h + 4) & 3, au1);

            // group 3 (kh=2): reads slots (h+1)&3 (ro0), (h+2)&3 (ro1) — untouched
            computeStage(0, 2, h);
            computeStage(1, 2, h);

            // epilogue: two rows
            #pragma unroll
            for (int nt = 0; nt < 4; nt++) {
                int oc = warpN * 32 + nt * 8 + 2 * t;
                #pragma unroll
                for (int mt = 0; mt < 4; mt++) {
                    int pix = cb + mt * 16 + g;
                    float* o0 = out + (((size_t)b * COUT + oc) * HH + h + rowOff) * WW + pix;
                    float* o1 = o0 + HW;
                    o0[0] = d[mt][nt][0];
                    o1[0] = d[mt][nt][1];
                    o0[8] = d[mt][nt][2];
                    o1[8] = d[mt][nt][3];
                }
            }
            // next iter's sync1 orders these stores/reads vs. next overwrites
        }
        p = segEndP;
    }
}

// ---------------- launch ----------------
extern "C" void kernel_launch(void* const* d_in, const int* in_sizes, int n_in,
                              void* d_out, int out_size) {
    const float* inputs = (const float*)d_in[0];   // [16,64,256,256]
    const float* weight = (const float*)d_in[1];   // [4,64,64,3,3]
    const float* fc_w   = (const float*)d_in[2];   // [4,64]
    const float* fc_b   = (const float*)d_in[3];   // [4]
    float* out = (float*)d_out;                    // [16,64,256,256]

    static int attr_set = 0;
    if (!attr_set) {
        cudaFuncSetAttribute(fused_kernel, cudaFuncAttributeMaxDynamicSharedMemorySize, SMEM_BYTES);
        attr_set = 1;
    }

    fused_kernel<<<NCTA, 512, SMEM_BYTES>>>(inputs, weight, fc_w, fc_b, out);
}